// round 14
// baseline (speedup 1.0000x reference)
#include <cuda_runtime.h>
#include <cuda_bf16.h>
#include <cstdint>
#include <math.h>

#define BB 4
#define SS 4096
#define DD 256
#define D2 512

// ---- scratch (static __device__ globals; no allocation anywhere) ----
__device__ __nv_bfloat16 g_q[(size_t)BB * SS * DD];    // q bf16 (8 MB)
__device__ __nv_bfloat16 g_k[(size_t)BB * SS * DD];    // k bf16 (8 MB)
__device__ __nv_bfloat16 g_P[(size_t)BB * SS * SS];    // exp(logits) bf16 (134 MB)
__device__ float         g_z[BB * SS];                 // per-row sum-exp
__device__ float         g_w[BB * SS];                 // column weights

// ===========================================================================
// helpers
// ===========================================================================
__device__ __forceinline__ uint32_t smem_u32(const void* p) {
    uint32_t a;
    asm("{ .reg .u64 t; cvta.to.shared.u64 t, %1; cvt.u32.u64 %0, t; }" : "=r"(a) : "l"(p));
    return a;
}
__device__ __forceinline__ void ldmx4(uint32_t* r, uint32_t addr) {
    asm volatile("ldmatrix.sync.aligned.m8n8.x4.shared.b16 {%0,%1,%2,%3}, [%4];"
                 : "=r"(r[0]), "=r"(r[1]), "=r"(r[2]), "=r"(r[3]) : "r"(addr));
}
__device__ __forceinline__ void ldmx2(uint32_t* r, uint32_t addr) {
    asm volatile("ldmatrix.sync.aligned.m8n8.x2.shared.b16 {%0,%1}, [%2];"
                 : "=r"(r[0]), "=r"(r[1]) : "r"(addr));
}
__device__ __forceinline__ void mma16816(float* c, const uint32_t* a, const uint32_t* b) {
    asm volatile(
        "mma.sync.aligned.m16n8k16.row.col.f32.bf16.bf16.f32 "
        "{%0,%1,%2,%3}, {%4,%5,%6,%7}, {%8,%9}, {%0,%1,%2,%3};"
        : "+f"(c[0]), "+f"(c[1]), "+f"(c[2]), "+f"(c[3])
        : "r"(a[0]), "r"(a[1]), "r"(a[2]), "r"(a[3]), "r"(b[0]), "r"(b[1]));
}
__device__ __forceinline__ uint32_t pack_bf16(float x, float y) {
    return (uint32_t)__bfloat16_as_ushort(__float2bfloat16_rn(x))
         | ((uint32_t)__bfloat16_as_ushort(__float2bfloat16_rn(y)) << 16);
}
__device__ __forceinline__ void cp_async16(uint32_t dst, const void* src) {
    asm volatile("cp.async.cg.shared.global [%0], [%1], 16;" :: "r"(dst), "l"(src) : "memory");
}
// exact bf16 -> fp32 (bit shift)
__device__ __forceinline__ float bflo(uint32_t w) { return __uint_as_float(w << 16); }
__device__ __forceinline__ float bfhi(uint32_t w) { return __uint_as_float(w & 0xFFFF0000u); }

#define PADB 80          // bytes per smem tile row (64B data + 16B pad)
// ---- logits (128q x 64k CTA) ----
#define LGS_B_OFF 10240                  // B rows start (A = 128 rows)
#define LGS_STAGE (10240 + 64 * PADB)    // 15360 B per stage
#define LG_SMEM   (3 * LGS_STAGE)        // 46080
#define EPI_STRIDE 144                   // staging row stride (bytes)
// ---- proj ----
#define PR_SMEM (2 * 128 * PADB)

// ===========================================================================
// projection: qk[B*S,512] = x @ W^T + bias, single bf16 HMMA.
// Head also zeros g_z / g_w / out (512 CTAs cover all slots).
// ===========================================================================
__global__ __launch_bounds__(256, 2) void proj_kernel(
    const float* __restrict__ x, const float* __restrict__ W,
    const float* __restrict__ bias, float* __restrict__ out, int n_out)
{
    __shared__ __align__(16) char tiles[PR_SMEM];

    const int tid = threadIdx.x;
    const int cta = blockIdx.y * gridDim.x + blockIdx.x;   // 0..511

    // ---- folded zeroing ----
    {
        int i = cta * 256 + tid;
        if (i < BB * SS) { g_z[i] = 0.0f; g_w[i] = 0.0f; }
        if (i < n_out)   out[i] = 0.0f;
    }

    const int lane = tid & 31, wid = tid >> 5;
    const int wm = wid >> 2, wn = wid & 3;

    const float* Ab = x + (size_t)blockIdx.y * 128 * DD;
    const float* Bb = W + (size_t)blockIdx.x * 128 * DD;
    const uint32_t sb = smem_u32(tiles);

    float acc[4][4][4];
#pragma unroll
    for (int m = 0; m < 4; m++)
#pragma unroll
        for (int n = 0; n < 4; n++)
#pragma unroll
            for (int u = 0; u < 4; u++) acc[m][n][u] = 0.0f;

    const uint32_t a_row = (uint32_t)(lane & 15);
    const uint32_t a_koff = (uint32_t)((lane >> 4) << 4);
    const uint32_t b_row = (uint32_t)(lane & 7);
    const uint32_t b_koff = (uint32_t)(((lane >> 3) & 1) << 4);

    for (int kt = 0; kt < 8; kt++) {
        __syncthreads();
#pragma unroll
        for (int i = 0; i < 8; i++) {
            int chunk = tid + i * 256;
            int arr = chunk >> 10;
            int c = chunk & 1023;
            int row = c >> 3, c4 = c & 7;
            const float* src = (arr ? Bb : Ab) + (size_t)row * DD + kt * 32 + c4 * 4;
            float4 v = *reinterpret_cast<const float4*>(src);
            uint2 p;
            p.x = pack_bf16(v.x, v.y);
            p.y = pack_bf16(v.z, v.w);
            *reinterpret_cast<uint2*>(tiles + arr * 10240 + row * PADB + c4 * 8) = p;
        }
        __syncthreads();

#pragma unroll
        for (int k16 = 0; k16 < 2; k16++) {
            const uint32_t kb = (uint32_t)(k16 * 32);
            uint32_t bh[4][2];
#pragma unroll
            for (int n = 0; n < 4; n++) {
                uint32_t boff = (uint32_t)(wn * 32 + n * 8 + b_row) * PADB + kb + b_koff;
                ldmx2(bh[n], sb + 10240 + boff);
            }
#pragma unroll
            for (int m = 0; m < 4; m++) {
                uint32_t aoff = (uint32_t)(wm * 64 + m * 16 + a_row) * PADB + kb + a_koff;
                uint32_t ah[4];
                ldmx4(ah, sb + aoff);
#pragma unroll
                for (int n = 0; n < 4; n++)
                    mma16816(acc[m][n], ah, bh[n]);
            }
        }
    }

    const int g = lane >> 2, t2 = (lane & 3) * 2;
#pragma unroll
    for (int m = 0; m < 4; m++) {
        const size_t grow = (size_t)blockIdx.y * 128 + wm * 64 + m * 16 + g;
#pragma unroll
        for (int n = 0; n < 4; n++) {
            const int col = blockIdx.x * 128 + wn * 32 + n * 8 + t2;
            const float b0 = bias[col], b1 = bias[col + 1];
            uint32_t p01 = pack_bf16(acc[m][n][0] + b0, acc[m][n][1] + b1);
            uint32_t p23 = pack_bf16(acc[m][n][2] + b0, acc[m][n][3] + b1);
            __nv_bfloat16* base = (col < DD) ? (g_q + col) : (g_k + (col - DD));
            *reinterpret_cast<uint32_t*>(base + grow * DD)       = p01;
            *reinterpret_cast<uint32_t*>(base + (grow + 8) * DD) = p23;
        }
    }
}

// ===========================================================================
// logits kernel (best config, per-batch launch): CTA = 128(q) x 64(k), K=256,
// single bf16 HMMA. 8 warps 4m x 2n, warp tile 32x32, 4 CTAs/SM (64-reg).
// 3-stage cp.async, hoisted ldmatrix bases.
// STAGED epilogue: exp -> smem (stride 144) -> 16B-coalesced store; z sums.
// ===========================================================================
__global__ __launch_bounds__(256, 4) void logits_kernel(const int b) {
    extern __shared__ __align__(16) char tiles[];
    __shared__ float zrow[128];

    const int tid = threadIdx.x;
    const int lane = tid & 31, wid = tid >> 5;
    const int wm = wid & 3, wn = wid >> 2;      // 4 m-groups x 2 n-groups
    const int nt = blockIdx.x, qt = blockIdx.y;

    if (tid < 128) zrow[tid] = 0.0f;

    const uint32_t sb = smem_u32(tiles);
    const __nv_bfloat16* Qs = g_q + ((size_t)b * SS + (size_t)qt * 128) * DD;
    const __nv_bfloat16* Ks = g_k + ((size_t)b * SS + (size_t)nt * 64) * DD;

    float acc[2][4][4];
#pragma unroll
    for (int m = 0; m < 2; m++)
#pragma unroll
        for (int n = 0; n < 4; n++)
#pragma unroll
            for (int u = 0; u < 4; u++) acc[m][n][u] = 0.0f;

    // hoisted per-thread ldmatrix base addresses (smem absolute, stage 0)
    const uint32_t x4_row = (uint32_t)(lane & 15);
    const uint32_t x4_koff = (uint32_t)((lane >> 4) << 4);
    const uint32_t a_base0 = sb + (uint32_t)(wm * 32 + x4_row) * PADB + x4_koff;
    const uint32_t a_base1 = a_base0 + 16 * PADB;
    const uint32_t b_base0 = sb + LGS_B_OFF + (uint32_t)(wn * 32 + x4_row) * PADB + x4_koff;
    const uint32_t b_base1 = b_base0 + 16 * PADB;

    const int ch_isB[3]  = { tid >= 512 ? 1 : 0, (tid + 256) >= 512 ? 1 : 0, 1 };

#define LOAD_STAGE(kt, s)                                                        \
    do {                                                                         \
        _Pragma("unroll")                                                        \
        for (int i = 0; i < 3; i++) {                                            \
            int chunk = tid + i * 256;                                           \
            int isB = ch_isB[i];                                                 \
            int c = chunk - (isB ? 512 : 0);                                     \
            int row = c >> 2, c4 = c & 3;                                        \
            const __nv_bfloat16* src = (isB ? Ks : Qs) + (size_t)row * DD + (kt) * 32 + c4 * 8; \
            cp_async16(sb + (uint32_t)(s) * LGS_STAGE + (isB ? LGS_B_OFF : 0) + row * PADB + c4 * 16, src); \
        }                                                                        \
        asm volatile("cp.async.commit_group;" ::: "memory");                     \
    } while (0)

    LOAD_STAGE(0, 0);
    LOAD_STAGE(1, 1);

    int stage = 0;
    for (int kt = 0; kt < 8; kt++) {
        if (kt < 7) asm volatile("cp.async.wait_group 1;" ::: "memory");
        else        asm volatile("cp.async.wait_group 0;" ::: "memory");
        __syncthreads();
        if (kt + 2 < 8) {
            int ns = stage + 2; if (ns >= 3) ns -= 3;
            LOAD_STAGE(kt + 2, ns);
        }

        const uint32_t soff = (uint32_t)stage * LGS_STAGE;
#pragma unroll
        for (int k16 = 0; k16 < 2; k16++) {
            const uint32_t kb = soff + (uint32_t)(k16 * 32);
            uint32_t br[2][4];
            ldmx4(br[0], b_base0 + kb);
            ldmx4(br[1], b_base1 + kb);
            uint32_t ah[4];
            ldmx4(ah, a_base0 + kb);
#pragma unroll
            for (int nn = 0; nn < 2; nn++) {
                uint32_t b0[2] = { br[nn][0], br[nn][2] };
                uint32_t b1[2] = { br[nn][1], br[nn][3] };
                mma16816(acc[0][nn * 2 + 0], ah, b0);
                mma16816(acc[0][nn * 2 + 1], ah, b1);
            }
            ldmx4(ah, a_base1 + kb);
#pragma unroll
            for (int nn = 0; nn < 2; nn++) {
                uint32_t b0[2] = { br[nn][0], br[nn][2] };
                uint32_t b1[2] = { br[nn][1], br[nn][3] };
                mma16816(acc[1][nn * 2 + 0], ah, b0);
                mma16816(acc[1][nn * 2 + 1], ah, b1);
            }
        }
        if (++stage == 3) stage = 0;
    }
    __syncthreads();   // mainloop reads done; smem becomes P staging

    // ---- epilogue: exp, pack to smem (128 rows x 64 bf16, stride 144) ----
    const int g = lane >> 2, t2 = (lane & 3) * 2;
#pragma unroll
    for (int m = 0; m < 2; m++) {
        const int row_lo = wm * 32 + m * 16 + g;
        float zlo = 0.0f, zhi = 0.0f;
#pragma unroll
        for (int n = 0; n < 4; n++) {
            float e0 = __expf(acc[m][n][0] * 0.0625f);
            float e1 = __expf(acc[m][n][1] * 0.0625f);
            float e2 = __expf(acc[m][n][2] * 0.0625f);
            float e3 = __expf(acc[m][n][3] * 0.0625f);
            zlo += e0 + e1;
            zhi += e2 + e3;
            const int col = wn * 32 + n * 8 + t2;
            *reinterpret_cast<uint32_t*>(tiles + row_lo * EPI_STRIDE + col * 2)       = pack_bf16(e0, e1);
            *reinterpret_cast<uint32_t*>(tiles + (row_lo + 8) * EPI_STRIDE + col * 2) = pack_bf16(e2, e3);
        }
        atomicAdd(&zrow[row_lo], zlo);
        atomicAdd(&zrow[row_lo + 8], zhi);
    }
    __syncthreads();

    // ---- coalesced 16B stores: 128 rows x 128 B = 1024 chunks, 4/thread ----
    const size_t grow0 = (size_t)b * SS + (size_t)qt * 128;
#pragma unroll
    for (int i = 0; i < 4; i++) {
        int chunk = tid + i * 256;
        int row = chunk >> 3, c16 = chunk & 7;
        uint4 v = *reinterpret_cast<const uint4*>(tiles + row * EPI_STRIDE + c16 * 16);
        *reinterpret_cast<uint4*>(g_P + (grow0 + row) * SS + nt * 64 + c16 * 8) = v;
    }
    if (tid < 128)
        atomicAdd(&g_z[grow0 + tid], zrow[tid]);
}

// ===========================================================================
// column weights (per-batch launch): w_k += sum_q P[q,k] / z_q.
// block = (512 q-rows) x (128 cols); 256 blocks per batch.
// ===========================================================================
__global__ __launch_bounds__(256) void col_weights_kernel(const int b) {
    __shared__ float izs[512];
    __shared__ float ws[16][128];

    const int tid = threadIdx.x;
    const int r0 = blockIdx.x * 512;
    const int c0 = blockIdx.y * 128;

    for (int i = tid; i < 512; i += 256)
        izs[i] = 1.0f / g_z[(size_t)b * SS + r0 + i];
    __syncthreads();

    const int c8 = tid & 15;
    const int rstripe = tid >> 4;

    float acc[8];
#pragma unroll
    for (int j = 0; j < 8; j++) acc[j] = 0.0f;

    const __nv_bfloat16* Pb = g_P + ((size_t)b * SS + r0 + rstripe) * SS + c0 + c8 * 8;
#pragma unroll 4
    for (int i = 0; i < 32; i++) {
        const float iz = izs[rstripe + i * 16];
        uint4 v = *reinterpret_cast<const uint4*>(Pb + (size_t)i * 16 * SS);
        const uint32_t w[4] = {v.x, v.y, v.z, v.w};
#pragma unroll
        for (int h = 0; h < 4; h++) {
            acc[2 * h]     = fmaf(bflo(w[h]), iz, acc[2 * h]);
            acc[2 * h + 1] = fmaf(bfhi(w[h]), iz, acc[2 * h + 1]);
        }
    }

#pragma unroll
    for (int j = 0; j < 8; j++) ws[rstripe][c8 * 8 + j] = acc[j];
    __syncthreads();

    if (tid < 128) {
        float s = 0.0f;
#pragma unroll
        for (int j = 0; j < 16; j++) s += ws[j][tid];
        atomicAdd(&g_w[(size_t)b * SS + c0 + tid], s);
    }
}

// ===========================================================================
// weighted pool: out[b,d] = sum_k w[b,k] * x[b,k,d]
// ===========================================================================
__global__ void out_kernel(const float* __restrict__ x, float* __restrict__ out) {
    const int b = blockIdx.y;
    const int k0 = blockIdx.x * 64;
    const int d = threadIdx.x;

    const float* xp = x + ((size_t)b * SS + k0) * DD + d;
    const float* wp = g_w + (size_t)b * SS + k0;
    float acc = 0.0f;
#pragma unroll 8
    for (int kk = 0; kk < 64; kk++)
        acc = fmaf(wp[kk], xp[(size_t)kk * DD], acc);
    atomicAdd(&out[b * DD + d], acc);
}

// ===========================================================================
extern "C" void kernel_launch(void* const* d_in, const int* in_sizes, int n_in,
                              void* d_out, int out_size) {
    const float* x    = (const float*)d_in[0];
    const float* W    = (const float*)d_in[1];
    const float* bias = (const float*)d_in[2];
    float* out = (float*)d_out;

    // one-time side-stream + events (host resources only; no device alloc)
    static cudaStream_t s2 = nullptr;
    static cudaEvent_t evL[BB];
    static cudaEvent_t evJoin;
    if (!s2) {
        cudaStreamCreateWithFlags(&s2, cudaStreamNonBlocking);
        for (int b = 0; b < BB; b++)
            cudaEventCreateWithFlags(&evL[b], cudaEventDisableTiming);
        cudaEventCreateWithFlags(&evJoin, cudaEventDisableTiming);
    }

    cudaFuncSetAttribute(logits_kernel, cudaFuncAttributeMaxDynamicSharedMemorySize, LG_SMEM);

    // 1) projection + folded zeroing (main stream)
    {
        dim3 grid(D2 / 128, (BB * SS) / 128);
        proj_kernel<<<grid, 256>>>(x, W, bias, out, out_size);
    }

    // 2) per-batch logits on main stream; colw_b forked onto s2 to overlap
    //    with logits of later batches.
    for (int b = 0; b < BB; b++) {
        dim3 gl(SS / 64, SS / 128, 1);
        logits_kernel<<<gl, 256, LG_SMEM>>>(b);
        cudaEventRecord(evL[b], 0);
        cudaStreamWaitEvent(s2, evL[b], 0);
        dim3 gc(SS / 512, SS / 128, 1);
        col_weights_kernel<<<gc, 256, 0, s2>>>(b);
    }

    // 3) join: out needs all column weights
    cudaEventRecord(evJoin, s2);
    cudaStreamWaitEvent(0, evJoin, 0);
    out_kernel<<<dim3(64, BB), 256>>>(x, out);
}

// round 15
// speedup vs baseline: 1.1677x; 1.1677x over previous
#include <cuda_runtime.h>
#include <cuda_bf16.h>
#include <cstdint>
#include <math.h>

#define BB 4
#define SS 4096
#define DD 256
#define D2 512

// ---- scratch (static __device__ globals; no allocation anywhere) ----
__device__ __nv_bfloat16 g_q[(size_t)BB * SS * DD];    // q bf16 (8 MB)
__device__ __nv_bfloat16 g_k[(size_t)BB * SS * DD];    // k bf16 (8 MB)
__device__ __nv_bfloat16 g_P[(size_t)BB * SS * SS];    // exp(logits) bf16 (134 MB)
__device__ float         g_z[BB * SS];                 // per-row sum-exp
__device__ float         g_w[BB * SS];                 // column weights

// ===========================================================================
// helpers
// ===========================================================================
__device__ __forceinline__ uint32_t smem_u32(const void* p) {
    uint32_t a;
    asm("{ .reg .u64 t; cvta.to.shared.u64 t, %1; cvt.u32.u64 %0, t; }" : "=r"(a) : "l"(p));
    return a;
}
__device__ __forceinline__ void ldmx4(uint32_t* r, uint32_t addr) {
    asm volatile("ldmatrix.sync.aligned.m8n8.x4.shared.b16 {%0,%1,%2,%3}, [%4];"
                 : "=r"(r[0]), "=r"(r[1]), "=r"(r[2]), "=r"(r[3]) : "r"(addr));
}
__device__ __forceinline__ void ldmx2(uint32_t* r, uint32_t addr) {
    asm volatile("ldmatrix.sync.aligned.m8n8.x2.shared.b16 {%0,%1}, [%2];"
                 : "=r"(r[0]), "=r"(r[1]) : "r"(addr));
}
__device__ __forceinline__ void mma16816(float* c, const uint32_t* a, const uint32_t* b) {
    asm volatile(
        "mma.sync.aligned.m16n8k16.row.col.f32.bf16.bf16.f32 "
        "{%0,%1,%2,%3}, {%4,%5,%6,%7}, {%8,%9}, {%0,%1,%2,%3};"
        : "+f"(c[0]), "+f"(c[1]), "+f"(c[2]), "+f"(c[3])
        : "r"(a[0]), "r"(a[1]), "r"(a[2]), "r"(a[3]), "r"(b[0]), "r"(b[1]));
}
__device__ __forceinline__ uint32_t pack_bf16(float x, float y) {
    return (uint32_t)__bfloat16_as_ushort(__float2bfloat16_rn(x))
         | ((uint32_t)__bfloat16_as_ushort(__float2bfloat16_rn(y)) << 16);
}
__device__ __forceinline__ void cp_async16(uint32_t dst, const void* src) {
    asm volatile("cp.async.cg.shared.global [%0], [%1], 16;" :: "r"(dst), "l"(src) : "memory");
}
// exact bf16 -> fp32 (bit shift)
__device__ __forceinline__ float bflo(uint32_t w) { return __uint_as_float(w << 16); }
__device__ __forceinline__ float bfhi(uint32_t w) { return __uint_as_float(w & 0xFFFF0000u); }

#define PADB 80          // bytes per smem tile row (64B data + 16B pad)
// ---- logits (128q x 64k CTA) ----
#define LGS_B_OFF 10240                  // B rows start (A = 128 rows)
#define LGS_STAGE (10240 + 64 * PADB)    // 15360 B per stage
#define LG_SMEM   (3 * LGS_STAGE)        // 46080
#define EPI_STRIDE 144                   // staging row stride (bytes)
// ---- proj ----
#define PR_SMEM (2 * 128 * PADB)

// ===========================================================================
// projection: qk[B*S,512] = x @ W^T + bias, single bf16 HMMA.
// Head zeros g_z / g_w / out. Mainloop register-double-buffered: LDG for
// k-tile kt+1 issued before the MMA section of kt (hides gmem latency).
// ===========================================================================
__global__ __launch_bounds__(256, 2) void proj_kernel(
    const float* __restrict__ x, const float* __restrict__ W,
    const float* __restrict__ bias, float* __restrict__ out, int n_out)
{
    __shared__ __align__(16) char tiles[PR_SMEM];

    const int tid = threadIdx.x;
    const int cta = blockIdx.y * gridDim.x + blockIdx.x;   // 0..511

    // ---- folded zeroing ----
    {
        int i = cta * 256 + tid;
        if (i < BB * SS) { g_z[i] = 0.0f; g_w[i] = 0.0f; }
        if (i < n_out)   out[i] = 0.0f;
    }

    const int lane = tid & 31, wid = tid >> 5;
    const int wm = wid >> 2, wn = wid & 3;

    const float* Ab = x + (size_t)blockIdx.y * 128 * DD;
    const float* Bb = W + (size_t)blockIdx.x * 128 * DD;
    const uint32_t sb = smem_u32(tiles);

    float acc[4][4][4];
#pragma unroll
    for (int m = 0; m < 4; m++)
#pragma unroll
        for (int n = 0; n < 4; n++)
#pragma unroll
            for (int u = 0; u < 4; u++) acc[m][n][u] = 0.0f;

    const uint32_t a_row = (uint32_t)(lane & 15);
    const uint32_t a_koff = (uint32_t)((lane >> 4) << 4);
    const uint32_t b_row = (uint32_t)(lane & 7);
    const uint32_t b_koff = (uint32_t)(((lane >> 3) & 1) << 4);

    // ---- register double-buffer: preload kt = 0 ----
    float4 vreg[8];
#pragma unroll
    for (int i = 0; i < 8; i++) {
        int chunk = tid + i * 256;
        int arr = chunk >> 10;
        int c = chunk & 1023;
        int row = c >> 3, c4 = c & 7;
        vreg[i] = *reinterpret_cast<const float4*>(
            (arr ? Bb : Ab) + (size_t)row * DD + c4 * 4);
    }

    for (int kt = 0; kt < 8; kt++) {
        __syncthreads();   // previous MMA reads done
        // convert + STS from registers
#pragma unroll
        for (int i = 0; i < 8; i++) {
            int chunk = tid + i * 256;
            int arr = chunk >> 10;
            int c = chunk & 1023;
            int row = c >> 3, c4 = c & 7;
            float4 v = vreg[i];
            uint2 p;
            p.x = pack_bf16(v.x, v.y);
            p.y = pack_bf16(v.z, v.w);
            *reinterpret_cast<uint2*>(tiles + arr * 10240 + row * PADB + c4 * 8) = p;
        }
        __syncthreads();

        // prefetch kt+1 into registers (flies behind the MMA section below)
        if (kt < 7) {
#pragma unroll
            for (int i = 0; i < 8; i++) {
                int chunk = tid + i * 256;
                int arr = chunk >> 10;
                int c = chunk & 1023;
                int row = c >> 3, c4 = c & 7;
                vreg[i] = *reinterpret_cast<const float4*>(
                    (arr ? Bb : Ab) + (size_t)row * DD + (kt + 1) * 32 + c4 * 4);
            }
        }

#pragma unroll
        for (int k16 = 0; k16 < 2; k16++) {
            const uint32_t kb = (uint32_t)(k16 * 32);
            uint32_t bh[4][2];
#pragma unroll
            for (int n = 0; n < 4; n++) {
                uint32_t boff = (uint32_t)(wn * 32 + n * 8 + b_row) * PADB + kb + b_koff;
                ldmx2(bh[n], sb + 10240 + boff);
            }
#pragma unroll
            for (int m = 0; m < 4; m++) {
                uint32_t aoff = (uint32_t)(wm * 64 + m * 16 + a_row) * PADB + kb + a_koff;
                uint32_t ah[4];
                ldmx4(ah, sb + aoff);
#pragma unroll
                for (int n = 0; n < 4; n++)
                    mma16816(acc[m][n], ah, bh[n]);
            }
        }
    }

    const int g = lane >> 2, t2 = (lane & 3) * 2;
#pragma unroll
    for (int m = 0; m < 4; m++) {
        const size_t grow = (size_t)blockIdx.y * 128 + wm * 64 + m * 16 + g;
#pragma unroll
        for (int n = 0; n < 4; n++) {
            const int col = blockIdx.x * 128 + wn * 32 + n * 8 + t2;
            const float b0 = bias[col], b1 = bias[col + 1];
            uint32_t p01 = pack_bf16(acc[m][n][0] + b0, acc[m][n][1] + b1);
            uint32_t p23 = pack_bf16(acc[m][n][2] + b0, acc[m][n][3] + b1);
            __nv_bfloat16* base = (col < DD) ? (g_q + col) : (g_k + (col - DD));
            *reinterpret_cast<uint32_t*>(base + grow * DD)       = p01;
            *reinterpret_cast<uint32_t*>(base + (grow + 8) * DD) = p23;
        }
    }
}

// ===========================================================================
// logits kernel (round-11/13 best config): CTA = 128(q) x 64(k), K=256,
// single bf16 HMMA. 8 warps 4m x 2n, warp tile 32x32, 4 CTAs/SM (64-reg).
// 3-stage cp.async, hoisted ldmatrix bases. ONE launch, grid z = BB.
// STAGED epilogue: exp -> smem (stride 144) -> 16B-coalesced store; z sums.
// ===========================================================================
__global__ __launch_bounds__(256, 4) void logits_kernel() {
    extern __shared__ __align__(16) char tiles[];
    __shared__ float zrow[128];

    const int tid = threadIdx.x;
    const int lane = tid & 31, wid = tid >> 5;
    const int wm = wid & 3, wn = wid >> 2;      // 4 m-groups x 2 n-groups
    const int nt = blockIdx.x, qt = blockIdx.y, b = blockIdx.z;

    if (tid < 128) zrow[tid] = 0.0f;

    const uint32_t sb = smem_u32(tiles);
    const __nv_bfloat16* Qs = g_q + ((size_t)b * SS + (size_t)qt * 128) * DD;
    const __nv_bfloat16* Ks = g_k + ((size_t)b * SS + (size_t)nt * 64) * DD;

    float acc[2][4][4];
#pragma unroll
    for (int m = 0; m < 2; m++)
#pragma unroll
        for (int n = 0; n < 4; n++)
#pragma unroll
            for (int u = 0; u < 4; u++) acc[m][n][u] = 0.0f;

    // hoisted per-thread ldmatrix base addresses (smem absolute, stage 0)
    const uint32_t x4_row = (uint32_t)(lane & 15);
    const uint32_t x4_koff = (uint32_t)((lane >> 4) << 4);
    const uint32_t a_base0 = sb + (uint32_t)(wm * 32 + x4_row) * PADB + x4_koff;
    const uint32_t a_base1 = a_base0 + 16 * PADB;
    const uint32_t b_base0 = sb + LGS_B_OFF + (uint32_t)(wn * 32 + x4_row) * PADB + x4_koff;
    const uint32_t b_base1 = b_base0 + 16 * PADB;

    const int ch_isB[3]  = { tid >= 512 ? 1 : 0, (tid + 256) >= 512 ? 1 : 0, 1 };

#define LOAD_STAGE(kt, s)                                                        \
    do {                                                                         \
        _Pragma("unroll")                                                        \
        for (int i = 0; i < 3; i++) {                                            \
            int chunk = tid + i * 256;                                           \
            int isB = ch_isB[i];                                                 \
            int c = chunk - (isB ? 512 : 0);                                     \
            int row = c >> 2, c4 = c & 3;                                        \
            const __nv_bfloat16* src = (isB ? Ks : Qs) + (size_t)row * DD + (kt) * 32 + c4 * 8; \
            cp_async16(sb + (uint32_t)(s) * LGS_STAGE + (isB ? LGS_B_OFF : 0) + row * PADB + c4 * 16, src); \
        }                                                                        \
        asm volatile("cp.async.commit_group;" ::: "memory");                     \
    } while (0)

    LOAD_STAGE(0, 0);
    LOAD_STAGE(1, 1);

    int stage = 0;
    for (int kt = 0; kt < 8; kt++) {
        if (kt < 7) asm volatile("cp.async.wait_group 1;" ::: "memory");
        else        asm volatile("cp.async.wait_group 0;" ::: "memory");
        __syncthreads();
        if (kt + 2 < 8) {
            int ns = stage + 2; if (ns >= 3) ns -= 3;
            LOAD_STAGE(kt + 2, ns);
        }

        const uint32_t soff = (uint32_t)stage * LGS_STAGE;
#pragma unroll
        for (int k16 = 0; k16 < 2; k16++) {
            const uint32_t kb = soff + (uint32_t)(k16 * 32);
            uint32_t br[2][4];
            ldmx4(br[0], b_base0 + kb);
            ldmx4(br[1], b_base1 + kb);
            uint32_t ah[4];
            ldmx4(ah, a_base0 + kb);
#pragma unroll
            for (int nn = 0; nn < 2; nn++) {
                uint32_t b0[2] = { br[nn][0], br[nn][2] };
                uint32_t b1[2] = { br[nn][1], br[nn][3] };
                mma16816(acc[0][nn * 2 + 0], ah, b0);
                mma16816(acc[0][nn * 2 + 1], ah, b1);
            }
            ldmx4(ah, a_base1 + kb);
#pragma unroll
            for (int nn = 0; nn < 2; nn++) {
                uint32_t b0[2] = { br[nn][0], br[nn][2] };
                uint32_t b1[2] = { br[nn][1], br[nn][3] };
                mma16816(acc[1][nn * 2 + 0], ah, b0);
                mma16816(acc[1][nn * 2 + 1], ah, b1);
            }
        }
        if (++stage == 3) stage = 0;
    }
    __syncthreads();   // mainloop reads done; smem becomes P staging

    // ---- epilogue: exp, pack to smem (128 rows x 64 bf16, stride 144) ----
    const int g = lane >> 2, t2 = (lane & 3) * 2;
#pragma unroll
    for (int m = 0; m < 2; m++) {
        const int row_lo = wm * 32 + m * 16 + g;
        float zlo = 0.0f, zhi = 0.0f;
#pragma unroll
        for (int n = 0; n < 4; n++) {
            float e0 = __expf(acc[m][n][0] * 0.0625f);
            float e1 = __expf(acc[m][n][1] * 0.0625f);
            float e2 = __expf(acc[m][n][2] * 0.0625f);
            float e3 = __expf(acc[m][n][3] * 0.0625f);
            zlo += e0 + e1;
            zhi += e2 + e3;
            const int col = wn * 32 + n * 8 + t2;
            *reinterpret_cast<uint32_t*>(tiles + row_lo * EPI_STRIDE + col * 2)       = pack_bf16(e0, e1);
            *reinterpret_cast<uint32_t*>(tiles + (row_lo + 8) * EPI_STRIDE + col * 2) = pack_bf16(e2, e3);
        }
        atomicAdd(&zrow[row_lo], zlo);
        atomicAdd(&zrow[row_lo + 8], zhi);
    }
    __syncthreads();

    // ---- coalesced 16B stores: 128 rows x 128 B = 1024 chunks, 4/thread ----
    const size_t grow0 = (size_t)b * SS + (size_t)qt * 128;
#pragma unroll
    for (int i = 0; i < 4; i++) {
        int chunk = tid + i * 256;
        int row = chunk >> 3, c16 = chunk & 7;
        uint4 v = *reinterpret_cast<const uint4*>(tiles + row * EPI_STRIDE + c16 * 16);
        *reinterpret_cast<uint4*>(g_P + (grow0 + row) * SS + nt * 64 + c16 * 8) = v;
    }
    if (tid < 128)
        atomicAdd(&g_z[grow0 + tid], zrow[tid]);
}

// ===========================================================================
// column weights: w_k += sum_q P[q,k] / z_q.  Column-partitioned:
// block = (512 q-rows) x (128 cols); 1024 blocks. Coalesced 256B row reads,
// register accumulators, smem cross-stripe reduce, 128 atomics/block.
// ===========================================================================
__global__ __launch_bounds__(256) void col_weights_kernel() {
    __shared__ float izs[512];
    __shared__ float ws[16][128];

    const int tid = threadIdx.x;
    const int r0 = blockIdx.x * 512;
    const int c0 = blockIdx.y * 128;
    const int b  = blockIdx.z;

    for (int i = tid; i < 512; i += 256)
        izs[i] = 1.0f / g_z[(size_t)b * SS + r0 + i];
    __syncthreads();

    const int c8 = tid & 15;
    const int rstripe = tid >> 4;

    float acc[8];
#pragma unroll
    for (int j = 0; j < 8; j++) acc[j] = 0.0f;

    const __nv_bfloat16* Pb = g_P + ((size_t)b * SS + r0 + rstripe) * SS + c0 + c8 * 8;
#pragma unroll 4
    for (int i = 0; i < 32; i++) {
        const float iz = izs[rstripe + i * 16];
        uint4 v = *reinterpret_cast<const uint4*>(Pb + (size_t)i * 16 * SS);
        const uint32_t w[4] = {v.x, v.y, v.z, v.w};
#pragma unroll
        for (int h = 0; h < 4; h++) {
            acc[2 * h]     = fmaf(bflo(w[h]), iz, acc[2 * h]);
            acc[2 * h + 1] = fmaf(bfhi(w[h]), iz, acc[2 * h + 1]);
        }
    }

#pragma unroll
    for (int j = 0; j < 8; j++) ws[rstripe][c8 * 8 + j] = acc[j];
    __syncthreads();

    if (tid < 128) {
        float s = 0.0f;
#pragma unroll
        for (int j = 0; j < 16; j++) s += ws[j][tid];
        atomicAdd(&g_w[(size_t)b * SS + c0 + tid], s);
    }
}

// ===========================================================================
// weighted pool: out[b,d] = sum_k w[b,k] * x[b,k,d]
// ===========================================================================
__global__ void out_kernel(const float* __restrict__ x, float* __restrict__ out) {
    const int b = blockIdx.y;
    const int k0 = blockIdx.x * 64;
    const int d = threadIdx.x;

    const float* xp = x + ((size_t)b * SS + k0) * DD + d;
    const float* wp = g_w + (size_t)b * SS + k0;
    float acc = 0.0f;
#pragma unroll 8
    for (int kk = 0; kk < 64; kk++)
        acc = fmaf(wp[kk], xp[(size_t)kk * DD], acc);
    atomicAdd(&out[b * DD + d], acc);
}

// ===========================================================================
extern "C" void kernel_launch(void* const* d_in, const int* in_sizes, int n_in,
                              void* d_out, int out_size) {
    const float* x    = (const float*)d_in[0];
    const float* W    = (const float*)d_in[1];
    const float* bias = (const float*)d_in[2];
    float* out = (float*)d_out;

    cudaFuncSetAttribute(logits_kernel, cudaFuncAttributeMaxDynamicSharedMemorySize, LG_SMEM);

    // 1) projection + folded zeroing (register double-buffered)
    {
        dim3 grid(D2 / 128, (BB * SS) / 128);
        proj_kernel<<<grid, 256>>>(x, W, bias, out, out_size);
    }

    // 2) logits + exp + z  (single launch, grid z = BB)
    {
        dim3 grid(SS / 64, SS / 128, BB);
        logits_kernel<<<grid, 256, LG_SMEM>>>();
    }

    // 3) column weights
    {
        dim3 grid(SS / 512, SS / 128, BB);
        col_weights_kernel<<<grid, 256>>>();
    }

    // 4) weighted pool
    out_kernel<<<dim3(64, BB), 256>>>(x, out);
}

// round 16
// speedup vs baseline: 1.1712x; 1.0031x over previous
#include <cuda_runtime.h>
#include <cuda_bf16.h>
#include <cstdint>
#include <math.h>

#define BB 4
#define SS 4096
#define DD 256
#define D2 512

// ---- scratch (static __device__ globals; no allocation anywhere) ----
__device__ __nv_bfloat16 g_q[(size_t)BB * SS * DD];    // q bf16 (8 MB)
__device__ __nv_bfloat16 g_k[(size_t)BB * SS * DD];    // k bf16 (8 MB)
__device__ __nv_bfloat16 g_P[(size_t)BB * SS * SS];    // exp(logits) bf16 (134 MB)
__device__ float         g_z[BB * SS];                 // per-row sum-exp
__device__ float         g_w[BB * SS];                 // column weights

// ===========================================================================
// helpers
// ===========================================================================
__device__ __forceinline__ uint32_t smem_u32(const void* p) {
    uint32_t a;
    asm("{ .reg .u64 t; cvta.to.shared.u64 t, %1; cvt.u32.u64 %0, t; }" : "=r"(a) : "l"(p));
    return a;
}
__device__ __forceinline__ void ldmx4(uint32_t* r, uint32_t addr) {
    asm volatile("ldmatrix.sync.aligned.m8n8.x4.shared.b16 {%0,%1,%2,%3}, [%4];"
                 : "=r"(r[0]), "=r"(r[1]), "=r"(r[2]), "=r"(r[3]) : "r"(addr));
}
__device__ __forceinline__ void ldmx2(uint32_t* r, uint32_t addr) {
    asm volatile("ldmatrix.sync.aligned.m8n8.x2.shared.b16 {%0,%1}, [%2];"
                 : "=r"(r[0]), "=r"(r[1]) : "r"(addr));
}
__device__ __forceinline__ void mma16816(float* c, const uint32_t* a, const uint32_t* b) {
    asm volatile(
        "mma.sync.aligned.m16n8k16.row.col.f32.bf16.bf16.f32 "
        "{%0,%1,%2,%3}, {%4,%5,%6,%7}, {%8,%9}, {%0,%1,%2,%3};"
        : "+f"(c[0]), "+f"(c[1]), "+f"(c[2]), "+f"(c[3])
        : "r"(a[0]), "r"(a[1]), "r"(a[2]), "r"(a[3]), "r"(b[0]), "r"(b[1]));
}
__device__ __forceinline__ uint32_t pack_bf16(float x, float y) {
    return (uint32_t)__bfloat16_as_ushort(__float2bfloat16_rn(x))
         | ((uint32_t)__bfloat16_as_ushort(__float2bfloat16_rn(y)) << 16);
}
__device__ __forceinline__ void cp_async16(uint32_t dst, const void* src) {
    asm volatile("cp.async.cg.shared.global [%0], [%1], 16;" :: "r"(dst), "l"(src) : "memory");
}
// exact bf16 -> fp32 (bit shift)
__device__ __forceinline__ float bflo(uint32_t w) { return __uint_as_float(w << 16); }
__device__ __forceinline__ float bfhi(uint32_t w) { return __uint_as_float(w & 0xFFFF0000u); }

#define PADB 80          // bytes per smem tile row (64B data + 16B pad)
// ---- logits (128q x 64k CTA) ----
#define LGS_B_OFF 10240                  // B rows start (A = 128 rows)
#define LGS_STAGE (10240 + 64 * PADB)    // 15360 B per stage
#define LG_SMEM   (3 * LGS_STAGE)        // 46080
#define EPI_STRIDE 144                   // staging row stride (bytes)
// ---- proj ----
#define PR_SMEM (2 * 128 * PADB)

// ===========================================================================
// projection: qk[B*S,512] = x @ W^T + bias, single bf16 HMMA.
// Head zeros g_z / g_w / out. Register double-buffered mainloop.
// ===========================================================================
__global__ __launch_bounds__(256, 2) void proj_kernel(
    const float* __restrict__ x, const float* __restrict__ W,
    const float* __restrict__ bias, float* __restrict__ out, int n_out)
{
    __shared__ __align__(16) char tiles[PR_SMEM];

    const int tid = threadIdx.x;
    const int cta = blockIdx.y * gridDim.x + blockIdx.x;   // 0..511

    // ---- folded zeroing ----
    {
        int i = cta * 256 + tid;
        if (i < BB * SS) { g_z[i] = 0.0f; g_w[i] = 0.0f; }
        if (i < n_out)   out[i] = 0.0f;
    }

    const int lane = tid & 31, wid = tid >> 5;
    const int wm = wid >> 2, wn = wid & 3;

    const float* Ab = x + (size_t)blockIdx.y * 128 * DD;
    const float* Bb = W + (size_t)blockIdx.x * 128 * DD;
    const uint32_t sb = smem_u32(tiles);

    float acc[4][4][4];
#pragma unroll
    for (int m = 0; m < 4; m++)
#pragma unroll
        for (int n = 0; n < 4; n++)
#pragma unroll
            for (int u = 0; u < 4; u++) acc[m][n][u] = 0.0f;

    const uint32_t a_row = (uint32_t)(lane & 15);
    const uint32_t a_koff = (uint32_t)((lane >> 4) << 4);
    const uint32_t b_row = (uint32_t)(lane & 7);
    const uint32_t b_koff = (uint32_t)(((lane >> 3) & 1) << 4);

    // ---- register double-buffer: preload kt = 0 ----
    float4 vreg[8];
#pragma unroll
    for (int i = 0; i < 8; i++) {
        int chunk = tid + i * 256;
        int arr = chunk >> 10;
        int c = chunk & 1023;
        int row = c >> 3, c4 = c & 7;
        vreg[i] = *reinterpret_cast<const float4*>(
            (arr ? Bb : Ab) + (size_t)row * DD + c4 * 4);
    }

    for (int kt = 0; kt < 8; kt++) {
        __syncthreads();   // previous MMA reads done
#pragma unroll
        for (int i = 0; i < 8; i++) {
            int chunk = tid + i * 256;
            int arr = chunk >> 10;
            int c = chunk & 1023;
            int row = c >> 3, c4 = c & 7;
            float4 v = vreg[i];
            uint2 p;
            p.x = pack_bf16(v.x, v.y);
            p.y = pack_bf16(v.z, v.w);
            *reinterpret_cast<uint2*>(tiles + arr * 10240 + row * PADB + c4 * 8) = p;
        }
        __syncthreads();

        if (kt < 7) {
#pragma unroll
            for (int i = 0; i < 8; i++) {
                int chunk = tid + i * 256;
                int arr = chunk >> 10;
                int c = chunk & 1023;
                int row = c >> 3, c4 = c & 7;
                vreg[i] = *reinterpret_cast<const float4*>(
                    (arr ? Bb : Ab) + (size_t)row * DD + (kt + 1) * 32 + c4 * 4);
            }
        }

#pragma unroll
        for (int k16 = 0; k16 < 2; k16++) {
            const uint32_t kb = (uint32_t)(k16 * 32);
            uint32_t bh[4][2];
#pragma unroll
            for (int n = 0; n < 4; n++) {
                uint32_t boff = (uint32_t)(wn * 32 + n * 8 + b_row) * PADB + kb + b_koff;
                ldmx2(bh[n], sb + 10240 + boff);
            }
#pragma unroll
            for (int m = 0; m < 4; m++) {
                uint32_t aoff = (uint32_t)(wm * 64 + m * 16 + a_row) * PADB + kb + a_koff;
                uint32_t ah[4];
                ldmx4(ah, sb + aoff);
#pragma unroll
                for (int n = 0; n < 4; n++)
                    mma16816(acc[m][n], ah, bh[n]);
            }
        }
    }

    const int g = lane >> 2, t2 = (lane & 3) * 2;
#pragma unroll
    for (int m = 0; m < 4; m++) {
        const size_t grow = (size_t)blockIdx.y * 128 + wm * 64 + m * 16 + g;
#pragma unroll
        for (int n = 0; n < 4; n++) {
            const int col = blockIdx.x * 128 + wn * 32 + n * 8 + t2;
            const float b0 = bias[col], b1 = bias[col + 1];
            uint32_t p01 = pack_bf16(acc[m][n][0] + b0, acc[m][n][1] + b1);
            uint32_t p23 = pack_bf16(acc[m][n][2] + b0, acc[m][n][3] + b1);
            __nv_bfloat16* base = (col < DD) ? (g_q + col) : (g_k + (col - DD));
            *reinterpret_cast<uint32_t*>(base + grow * DD)       = p01;
            *reinterpret_cast<uint32_t*>(base + (grow + 8) * DD) = p23;
        }
    }
}

// ===========================================================================
// logits kernel (best config): CTA = 128(q) x 64(k), K=256, single bf16 HMMA.
// 8 warps 4m x 2n, warp tile 32x32, 4 CTAs/SM (64-reg). 3-stage cp.async,
// hoisted ldmatrix bases. ONE launch, grid z = BB.
// STAGED epilogue: exp -> smem (stride 144) -> 16B-coalesced store; z sums.
// ===========================================================================
__global__ __launch_bounds__(256, 4) void logits_kernel() {
    extern __shared__ __align__(16) char tiles[];
    __shared__ float zrow[128];

    const int tid = threadIdx.x;
    const int lane = tid & 31, wid = tid >> 5;
    const int wm = wid & 3, wn = wid >> 2;      // 4 m-groups x 2 n-groups
    const int nt = blockIdx.x, qt = blockIdx.y, b = blockIdx.z;

    if (tid < 128) zrow[tid] = 0.0f;

    const uint32_t sb = smem_u32(tiles);
    const __nv_bfloat16* Qs = g_q + ((size_t)b * SS + (size_t)qt * 128) * DD;
    const __nv_bfloat16* Ks = g_k + ((size_t)b * SS + (size_t)nt * 64) * DD;

    float acc[2][4][4];
#pragma unroll
    for (int m = 0; m < 2; m++)
#pragma unroll
        for (int n = 0; n < 4; n++)
#pragma unroll
            for (int u = 0; u < 4; u++) acc[m][n][u] = 0.0f;

    // hoisted per-thread ldmatrix base addresses (smem absolute, stage 0)
    const uint32_t x4_row = (uint32_t)(lane & 15);
    const uint32_t x4_koff = (uint32_t)((lane >> 4) << 4);
    const uint32_t a_base0 = sb + (uint32_t)(wm * 32 + x4_row) * PADB + x4_koff;
    const uint32_t a_base1 = a_base0 + 16 * PADB;
    const uint32_t b_base0 = sb + LGS_B_OFF + (uint32_t)(wn * 32 + x4_row) * PADB + x4_koff;
    const uint32_t b_base1 = b_base0 + 16 * PADB;

    const int ch_isB[3]  = { tid >= 512 ? 1 : 0, (tid + 256) >= 512 ? 1 : 0, 1 };

#define LOAD_STAGE(kt, s)                                                        \
    do {                                                                         \
        _Pragma("unroll")                                                        \
        for (int i = 0; i < 3; i++) {                                            \
            int chunk = tid + i * 256;                                           \
            int isB = ch_isB[i];                                                 \
            int c = chunk - (isB ? 512 : 0);                                     \
            int row = c >> 2, c4 = c & 3;                                        \
            const __nv_bfloat16* src = (isB ? Ks : Qs) + (size_t)row * DD + (kt) * 32 + c4 * 8; \
            cp_async16(sb + (uint32_t)(s) * LGS_STAGE + (isB ? LGS_B_OFF : 0) + row * PADB + c4 * 16, src); \
        }                                                                        \
        asm volatile("cp.async.commit_group;" ::: "memory");                     \
    } while (0)

    LOAD_STAGE(0, 0);
    LOAD_STAGE(1, 1);

    int stage = 0;
    for (int kt = 0; kt < 8; kt++) {
        if (kt < 7) asm volatile("cp.async.wait_group 1;" ::: "memory");
        else        asm volatile("cp.async.wait_group 0;" ::: "memory");
        __syncthreads();
        if (kt + 2 < 8) {
            int ns = stage + 2; if (ns >= 3) ns -= 3;
            LOAD_STAGE(kt + 2, ns);
        }

        const uint32_t soff = (uint32_t)stage * LGS_STAGE;
#pragma unroll
        for (int k16 = 0; k16 < 2; k16++) {
            const uint32_t kb = soff + (uint32_t)(k16 * 32);
            uint32_t br[2][4];
            ldmx4(br[0], b_base0 + kb);
            ldmx4(br[1], b_base1 + kb);
            uint32_t ah[4];
            ldmx4(ah, a_base0 + kb);
#pragma unroll
            for (int nn = 0; nn < 2; nn++) {
                uint32_t b0[2] = { br[nn][0], br[nn][2] };
                uint32_t b1[2] = { br[nn][1], br[nn][3] };
                mma16816(acc[0][nn * 2 + 0], ah, b0);
                mma16816(acc[0][nn * 2 + 1], ah, b1);
            }
            ldmx4(ah, a_base1 + kb);
#pragma unroll
            for (int nn = 0; nn < 2; nn++) {
                uint32_t b0[2] = { br[nn][0], br[nn][2] };
                uint32_t b1[2] = { br[nn][1], br[nn][3] };
                mma16816(acc[1][nn * 2 + 0], ah, b0);
                mma16816(acc[1][nn * 2 + 1], ah, b1);
            }
        }
        if (++stage == 3) stage = 0;
    }
    __syncthreads();   // mainloop reads done; smem becomes P staging

    // ---- epilogue: exp, pack to smem (128 rows x 64 bf16, stride 144) ----
    const int g = lane >> 2, t2 = (lane & 3) * 2;
#pragma unroll
    for (int m = 0; m < 2; m++) {
        const int row_lo = wm * 32 + m * 16 + g;
        float zlo = 0.0f, zhi = 0.0f;
#pragma unroll
        for (int n = 0; n < 4; n++) {
            float e0 = __expf(acc[m][n][0] * 0.0625f);
            float e1 = __expf(acc[m][n][1] * 0.0625f);
            float e2 = __expf(acc[m][n][2] * 0.0625f);
            float e3 = __expf(acc[m][n][3] * 0.0625f);
            zlo += e0 + e1;
            zhi += e2 + e3;
            const int col = wn * 32 + n * 8 + t2;
            *reinterpret_cast<uint32_t*>(tiles + row_lo * EPI_STRIDE + col * 2)       = pack_bf16(e0, e1);
            *reinterpret_cast<uint32_t*>(tiles + (row_lo + 8) * EPI_STRIDE + col * 2) = pack_bf16(e2, e3);
        }
        atomicAdd(&zrow[row_lo], zlo);
        atomicAdd(&zrow[row_lo + 8], zhi);
    }
    __syncthreads();

    // ---- coalesced 16B stores: 128 rows x 128 B = 1024 chunks, 4/thread ----
    const size_t grow0 = (size_t)b * SS + (size_t)qt * 128;
#pragma unroll
    for (int i = 0; i < 4; i++) {
        int chunk = tid + i * 256;
        int row = chunk >> 3, c16 = chunk & 7;
        uint4 v = *reinterpret_cast<const uint4*>(tiles + row * EPI_STRIDE + c16 * 16);
        *reinterpret_cast<uint4*>(g_P + (grow0 + row) * SS + nt * 64 + c16 * 8) = v;
    }
    if (tid < 128)
        atomicAdd(&g_z[grow0 + tid], zrow[tid]);
}

// ===========================================================================
// column weights: w_k += sum_q P[q,k] / z_q.  Column-partitioned:
// block = (512 q-rows) x (128 cols); 1024 blocks. unroll 8 -> 8 loads in
// flight per thread (MLP-bound fix).
// ===========================================================================
__global__ __launch_bounds__(256) void col_weights_kernel() {
    __shared__ float izs[512];
    __shared__ float ws[16][128];

    const int tid = threadIdx.x;
    const int r0 = blockIdx.x * 512;
    const int c0 = blockIdx.y * 128;
    const int b  = blockIdx.z;

    for (int i = tid; i < 512; i += 256)
        izs[i] = 1.0f / g_z[(size_t)b * SS + r0 + i];
    __syncthreads();

    const int c8 = tid & 15;
    const int rstripe = tid >> 4;

    float acc[8];
#pragma unroll
    for (int j = 0; j < 8; j++) acc[j] = 0.0f;

    const __nv_bfloat16* Pb = g_P + ((size_t)b * SS + r0 + rstripe) * SS + c0 + c8 * 8;
#pragma unroll 8
    for (int i = 0; i < 32; i++) {
        const float iz = izs[rstripe + i * 16];
        uint4 v = *reinterpret_cast<const uint4*>(Pb + (size_t)i * 16 * SS);
        const uint32_t w[4] = {v.x, v.y, v.z, v.w};
#pragma unroll
        for (int h = 0; h < 4; h++) {
            acc[2 * h]     = fmaf(bflo(w[h]), iz, acc[2 * h]);
            acc[2 * h + 1] = fmaf(bfhi(w[h]), iz, acc[2 * h + 1]);
        }
    }

#pragma unroll
    for (int j = 0; j < 8; j++) ws[rstripe][c8 * 8 + j] = acc[j];
    __syncthreads();

    if (tid < 128) {
        float s = 0.0f;
#pragma unroll
        for (int j = 0; j < 16; j++) s += ws[j][tid];
        atomicAdd(&g_w[(size_t)b * SS + c0 + tid], s);
    }
}

// ===========================================================================
// weighted pool: out[b,d] = sum_k w[b,k] * x[b,k,d].
// 512 blocks (32 keys each), 4 independent accumulator chains.
// ===========================================================================
__global__ __launch_bounds__(256) void out_kernel(
    const float* __restrict__ x, float* __restrict__ out)
{
    const int b = blockIdx.y;
    const int k0 = blockIdx.x * 32;
    const int d = threadIdx.x;

    const float* xp = x + ((size_t)b * SS + k0) * DD + d;
    const float* wp = g_w + (size_t)b * SS + k0;

    float a0 = 0.0f, a1 = 0.0f, a2 = 0.0f, a3 = 0.0f;
#pragma unroll
    for (int kk = 0; kk < 32; kk += 4) {
        a0 = fmaf(wp[kk + 0], xp[(size_t)(kk + 0) * DD], a0);
        a1 = fmaf(wp[kk + 1], xp[(size_t)(kk + 1) * DD], a1);
        a2 = fmaf(wp[kk + 2], xp[(size_t)(kk + 2) * DD], a2);
        a3 = fmaf(wp[kk + 3], xp[(size_t)(kk + 3) * DD], a3);
    }
    atomicAdd(&out[b * DD + d], (a0 + a1) + (a2 + a3));
}

// ===========================================================================
extern "C" void kernel_launch(void* const* d_in, const int* in_sizes, int n_in,
                              void* d_out, int out_size) {
    const float* x    = (const float*)d_in[0];
    const float* W    = (const float*)d_in[1];
    const float* bias = (const float*)d_in[2];
    float* out = (float*)d_out;

    cudaFuncSetAttribute(logits_kernel, cudaFuncAttributeMaxDynamicSharedMemorySize, LG_SMEM);

    // 1) projection + folded zeroing (register double-buffered)
    {
        dim3 grid(D2 / 128, (BB * SS) / 128);
        proj_kernel<<<grid, 256>>>(x, W, bias, out, out_size);
    }

    // 2) logits + exp + z  (single launch, grid z = BB)
    {
        dim3 grid(SS / 64, SS / 128, BB);
        logits_kernel<<<grid, 256, LG_SMEM>>>();
    }

    // 3) column weights (unroll 8)
    {
        dim3 grid(SS / 512, SS / 128, BB);
        col_weights_kernel<<<grid, 256>>>();
    }

    // 4) weighted pool (512 blocks, 4 acc chains)
    out_kernel<<<dim3(SS / 32, BB), 256>>>(x, out);
}

// round 17
// speedup vs baseline: 1.2393x; 1.0581x over previous
#include <cuda_runtime.h>
#include <cuda_bf16.h>
#include <cstdint>
#include <math.h>

#define BB 4
#define SS 4096
#define DD 256
#define D2 512

// ---- scratch (static __device__ globals; no allocation anywhere) ----
__device__ __nv_bfloat16 g_xb[(size_t)BB * SS * DD];   // x bf16 (8 MB)
__device__ __nv_bfloat16 g_Wb[(size_t)D2 * DD];        // W bf16 (256 KB)
__device__ __nv_bfloat16 g_q[(size_t)BB * SS * DD];    // q bf16 (8 MB)
__device__ __nv_bfloat16 g_k[(size_t)BB * SS * DD];    // k bf16 (8 MB)
__device__ __nv_bfloat16 g_P[(size_t)BB * SS * SS];    // exp(logits) bf16 (134 MB)
__device__ float         g_z[BB * SS];                 // per-row sum-exp
__device__ float         g_w[BB * SS];                 // column weights

// ===========================================================================
// helpers
// ===========================================================================
__device__ __forceinline__ uint32_t smem_u32(const void* p) {
    uint32_t a;
    asm("{ .reg .u64 t; cvta.to.shared.u64 t, %1; cvt.u32.u64 %0, t; }" : "=r"(a) : "l"(p));
    return a;
}
__device__ __forceinline__ void ldmx4(uint32_t* r, uint32_t addr) {
    asm volatile("ldmatrix.sync.aligned.m8n8.x4.shared.b16 {%0,%1,%2,%3}, [%4];"
                 : "=r"(r[0]), "=r"(r[1]), "=r"(r[2]), "=r"(r[3]) : "r"(addr));
}
__device__ __forceinline__ void ldmx2(uint32_t* r, uint32_t addr) {
    asm volatile("ldmatrix.sync.aligned.m8n8.x2.shared.b16 {%0,%1}, [%2];"
                 : "=r"(r[0]), "=r"(r[1]) : "r"(addr));
}
__device__ __forceinline__ void mma16816(float* c, const uint32_t* a, const uint32_t* b) {
    asm volatile(
        "mma.sync.aligned.m16n8k16.row.col.f32.bf16.bf16.f32 "
        "{%0,%1,%2,%3}, {%4,%5,%6,%7}, {%8,%9}, {%0,%1,%2,%3};"
        : "+f"(c[0]), "+f"(c[1]), "+f"(c[2]), "+f"(c[3])
        : "r"(a[0]), "r"(a[1]), "r"(a[2]), "r"(a[3]), "r"(b[0]), "r"(b[1]));
}
__device__ __forceinline__ uint32_t pack_bf16(float x, float y) {
    return (uint32_t)__bfloat16_as_ushort(__float2bfloat16_rn(x))
         | ((uint32_t)__bfloat16_as_ushort(__float2bfloat16_rn(y)) << 16);
}
__device__ __forceinline__ void cp_async16(uint32_t dst, const void* src) {
    asm volatile("cp.async.cg.shared.global [%0], [%1], 16;" :: "r"(dst), "l"(src) : "memory");
}
// exact bf16 -> fp32 (bit shift)
__device__ __forceinline__ float bflo(uint32_t w) { return __uint_as_float(w << 16); }
__device__ __forceinline__ float bfhi(uint32_t w) { return __uint_as_float(w & 0xFFFF0000u); }

#define PADB 80          // bytes per smem tile row (64B data + 16B pad)
// ---- logits (128q x 64k CTA) ----
#define LGS_B_OFF 10240                  // B rows start (A = 128 rows)
#define LGS_STAGE (10240 + 64 * PADB)    // 15360 B per stage
#define LG_SMEM   (3 * LGS_STAGE)        // 46080
#define EPI_STRIDE 144                   // staging row stride (bytes)
// ---- proj (128 x 128 CTA, A 128 rows + B 128 rows per stage) ----
#define PJ_B_OFF  10240
#define PJ_STAGE  20480
#define PJ_SMEM   (3 * PJ_STAGE)         // 61440

// ===========================================================================
// convert: x, W -> bf16; also zeros g_z / g_w / out.
// 1081344 float4 chunks total (x: 1048576, W: 32768) -> grid 4224 x 256.
// ===========================================================================
#define NX4 (BB * SS * DD / 4)
__global__ __launch_bounds__(256) void convert_kernel(
    const float* __restrict__ x, const float* __restrict__ W,
    float* __restrict__ out, int n_out)
{
    int i = blockIdx.x * 256 + threadIdx.x;
    if (i < BB * SS) { g_z[i] = 0.0f; g_w[i] = 0.0f; }
    if (i < n_out)   out[i] = 0.0f;

    float4 v;
    __nv_bfloat16* dst;
    if (i < NX4) {
        v = reinterpret_cast<const float4*>(x)[i];
        dst = g_xb + (size_t)i * 4;
    } else {
        int j = i - NX4;                    // 0 .. 32767
        v = reinterpret_cast<const float4*>(W)[j];
        dst = g_Wb + (size_t)j * 4;
    }
    uint2 p;
    p.x = pack_bf16(v.x, v.y);
    p.y = pack_bf16(v.z, v.w);
    *reinterpret_cast<uint2*>(dst) = p;
}

// ===========================================================================
// projection: qk[B*S,512] = x @ W^T + bias from PRE-CONVERTED bf16 inputs.
// CTA 128(rows) x 128(cols), 8 warps 2m x 4n (warp 64x32), K=256, BK=32.
// 3-stage cp.async pipeline (61.4 KB), one barrier per k-tile, 2 CTAs/SM.
// ===========================================================================
__global__ __launch_bounds__(256, 2) void proj_kernel(const float* __restrict__ bias)
{
    extern __shared__ __align__(16) char tiles[];

    const int tid = threadIdx.x;
    const int lane = tid & 31, wid = tid >> 5;
    const int wm = wid >> 2, wn = wid & 3;

    const __nv_bfloat16* Ab = g_xb + (size_t)blockIdx.y * 128 * DD;
    const __nv_bfloat16* Bb = g_Wb + (size_t)blockIdx.x * 128 * DD;
    const uint32_t sb = smem_u32(tiles);

    float acc[4][4][4];
#pragma unroll
    for (int m = 0; m < 4; m++)
#pragma unroll
        for (int n = 0; n < 4; n++)
#pragma unroll
            for (int u = 0; u < 4; u++) acc[m][n][u] = 0.0f;

    const uint32_t a_row = (uint32_t)(lane & 15);
    const uint32_t a_koff = (uint32_t)((lane >> 4) << 4);
    const uint32_t b_row = (uint32_t)(lane & 7);
    const uint32_t b_koff = (uint32_t)(((lane >> 3) & 1) << 4);

    // stage loader: 1024 x 16B chunks (A 512 | B 512), 4 per thread
#define PJ_LOAD(kt, s)                                                           \
    do {                                                                         \
        _Pragma("unroll")                                                        \
        for (int i = 0; i < 4; i++) {                                            \
            int chunk = tid + i * 256;                                           \
            int arr = chunk >> 9;                                                \
            int c = chunk & 511;                                                 \
            int row = c >> 2, c4 = c & 3;                                        \
            const __nv_bfloat16* src = (arr ? Bb : Ab) + (size_t)row * DD + (kt) * 32 + c4 * 8; \
            cp_async16(sb + (uint32_t)(s) * PJ_STAGE + (arr ? PJ_B_OFF : 0) + row * PADB + c4 * 16, src); \
        }                                                                        \
        asm volatile("cp.async.commit_group;" ::: "memory");                     \
    } while (0)

    PJ_LOAD(0, 0);
    PJ_LOAD(1, 1);

    int stage = 0;
    for (int kt = 0; kt < 8; kt++) {
        if (kt < 7) asm volatile("cp.async.wait_group 1;" ::: "memory");
        else        asm volatile("cp.async.wait_group 0;" ::: "memory");
        __syncthreads();
        if (kt + 2 < 8) {
            int ns = stage + 2; if (ns >= 3) ns -= 3;
            PJ_LOAD(kt + 2, ns);
        }

        const uint32_t st = sb + (uint32_t)stage * PJ_STAGE;
#pragma unroll
        for (int k16 = 0; k16 < 2; k16++) {
            const uint32_t kb = (uint32_t)(k16 * 32);
            uint32_t bh[4][2];
#pragma unroll
            for (int n = 0; n < 4; n++) {
                uint32_t boff = (uint32_t)(wn * 32 + n * 8 + b_row) * PADB + kb + b_koff;
                ldmx2(bh[n], st + PJ_B_OFF + boff);
            }
#pragma unroll
            for (int m = 0; m < 4; m++) {
                uint32_t aoff = (uint32_t)(wm * 64 + m * 16 + a_row) * PADB + kb + a_koff;
                uint32_t ah[4];
                ldmx4(ah, st + aoff);
#pragma unroll
                for (int n = 0; n < 4; n++)
                    mma16816(acc[m][n], ah, bh[n]);
            }
        }
        if (++stage == 3) stage = 0;
    }

    const int g = lane >> 2, t2 = (lane & 3) * 2;
#pragma unroll
    for (int m = 0; m < 4; m++) {
        const size_t grow = (size_t)blockIdx.y * 128 + wm * 64 + m * 16 + g;
#pragma unroll
        for (int n = 0; n < 4; n++) {
            const int col = blockIdx.x * 128 + wn * 32 + n * 8 + t2;
            const float b0 = bias[col], b1 = bias[col + 1];
            uint32_t p01 = pack_bf16(acc[m][n][0] + b0, acc[m][n][1] + b1);
            uint32_t p23 = pack_bf16(acc[m][n][2] + b0, acc[m][n][3] + b1);
            __nv_bfloat16* base = (col < DD) ? (g_q + col) : (g_k + (col - DD));
            *reinterpret_cast<uint32_t*>(base + grow * DD)       = p01;
            *reinterpret_cast<uint32_t*>(base + (grow + 8) * DD) = p23;
        }
    }
}

// ===========================================================================
// logits kernel (best config): CTA = 128(q) x 64(k), K=256, single bf16 HMMA.
// 8 warps 4m x 2n, warp tile 32x32, 4 CTAs/SM (64-reg). 3-stage cp.async,
// hoisted ldmatrix bases. ONE launch, grid z = BB.
// STAGED epilogue: exp -> smem -> 16B-coalesced STREAMING store; z sums.
// ===========================================================================
__global__ __launch_bounds__(256, 4) void logits_kernel() {
    extern __shared__ __align__(16) char tiles[];
    __shared__ float zrow[128];

    const int tid = threadIdx.x;
    const int lane = tid & 31, wid = tid >> 5;
    const int wm = wid & 3, wn = wid >> 2;      // 4 m-groups x 2 n-groups
    const int nt = blockIdx.x, qt = blockIdx.y, b = blockIdx.z;

    if (tid < 128) zrow[tid] = 0.0f;

    const uint32_t sb = smem_u32(tiles);
    const __nv_bfloat16* Qs = g_q + ((size_t)b * SS + (size_t)qt * 128) * DD;
    const __nv_bfloat16* Ks = g_k + ((size_t)b * SS + (size_t)nt * 64) * DD;

    float acc[2][4][4];
#pragma unroll
    for (int m = 0; m < 2; m++)
#pragma unroll
        for (int n = 0; n < 4; n++)
#pragma unroll
            for (int u = 0; u < 4; u++) acc[m][n][u] = 0.0f;

    // hoisted per-thread ldmatrix base addresses (smem absolute, stage 0)
    const uint32_t x4_row = (uint32_t)(lane & 15);
    const uint32_t x4_koff = (uint32_t)((lane >> 4) << 4);
    const uint32_t a_base0 = sb + (uint32_t)(wm * 32 + x4_row) * PADB + x4_koff;
    const uint32_t a_base1 = a_base0 + 16 * PADB;
    const uint32_t b_base0 = sb + LGS_B_OFF + (uint32_t)(wn * 32 + x4_row) * PADB + x4_koff;
    const uint32_t b_base1 = b_base0 + 16 * PADB;

    const int ch_isB[3]  = { tid >= 512 ? 1 : 0, (tid + 256) >= 512 ? 1 : 0, 1 };

#define LOAD_STAGE(kt, s)                                                        \
    do {                                                                         \
        _Pragma("unroll")                                                        \
        for (int i = 0; i < 3; i++) {                                            \
            int chunk = tid + i * 256;                                           \
            int isB = ch_isB[i];                                                 \
            int c = chunk - (isB ? 512 : 0);                                     \
            int row = c >> 2, c4 = c & 3;                                        \
            const __nv_bfloat16* src = (isB ? Ks : Qs) + (size_t)row * DD + (kt) * 32 + c4 * 8; \
            cp_async16(sb + (uint32_t)(s) * LGS_STAGE + (isB ? LGS_B_OFF : 0) + row * PADB + c4 * 16, src); \
        }                                                                        \
        asm volatile("cp.async.commit_group;" ::: "memory");                     \
    } while (0)

    LOAD_STAGE(0, 0);
    LOAD_STAGE(1, 1);

    int stage = 0;
    for (int kt = 0; kt < 8; kt++) {
        if (kt < 7) asm volatile("cp.async.wait_group 1;" ::: "memory");
        else        asm volatile("cp.async.wait_group 0;" ::: "memory");
        __syncthreads();
        if (kt + 2 < 8) {
            int ns = stage + 2; if (ns >= 3) ns -= 3;
            LOAD_STAGE(kt + 2, ns);
        }

        const uint32_t soff = (uint32_t)stage * LGS_STAGE;
#pragma unroll
        for (int k16 = 0; k16 < 2; k16++) {
            const uint32_t kb = soff + (uint32_t)(k16 * 32);
            uint32_t br[2][4];
            ldmx4(br[0], b_base0 + kb);
            ldmx4(br[1], b_base1 + kb);
            uint32_t ah[4];
            ldmx4(ah, a_base0 + kb);
#pragma unroll
            for (int nn = 0; nn < 2; nn++) {
                uint32_t b0[2] = { br[nn][0], br[nn][2] };
                uint32_t b1[2] = { br[nn][1], br[nn][3] };
                mma16816(acc[0][nn * 2 + 0], ah, b0);
                mma16816(acc[0][nn * 2 + 1], ah, b1);
            }
            ldmx4(ah, a_base1 + kb);
#pragma unroll
            for (int nn = 0; nn < 2; nn++) {
                uint32_t b0[2] = { br[nn][0], br[nn][2] };
                uint32_t b1[2] = { br[nn][1], br[nn][3] };
                mma16816(acc[1][nn * 2 + 0], ah, b0);
                mma16816(acc[1][nn * 2 + 1], ah, b1);
            }
        }
        if (++stage == 3) stage = 0;
    }
    __syncthreads();   // mainloop reads done; smem becomes P staging

    // ---- epilogue: exp, pack to smem (128 rows x 64 bf16, stride 144) ----
    const int g = lane >> 2, t2 = (lane & 3) * 2;
#pragma unroll
    for (int m = 0; m < 2; m++) {
        const int row_lo = wm * 32 + m * 16 + g;
        float zlo = 0.0f, zhi = 0.0f;
#pragma unroll
        for (int n = 0; n < 4; n++) {
            float e0 = __expf(acc[m][n][0] * 0.0625f);
            float e1 = __expf(acc[m][n][1] * 0.0625f);
            float e2 = __expf(acc[m][n][2] * 0.0625f);
            float e3 = __expf(acc[m][n][3] * 0.0625f);
            zlo += e0 + e1;
            zhi += e2 + e3;
            const int col = wn * 32 + n * 8 + t2;
            *reinterpret_cast<uint32_t*>(tiles + row_lo * EPI_STRIDE + col * 2)       = pack_bf16(e0, e1);
            *reinterpret_cast<uint32_t*>(tiles + (row_lo + 8) * EPI_STRIDE + col * 2) = pack_bf16(e2, e3);
        }
        atomicAdd(&zrow[row_lo], zlo);
        atomicAdd(&zrow[row_lo + 8], zhi);
    }
    __syncthreads();

    // ---- coalesced 16B STREAMING stores (P is a one-shot 134MB stream) ----
    const size_t grow0 = (size_t)b * SS + (size_t)qt * 128;
#pragma unroll
    for (int i = 0; i < 4; i++) {
        int chunk = tid + i * 256;
        int row = chunk >> 3, c16 = chunk & 7;
        uint4 v = *reinterpret_cast<const uint4*>(tiles + row * EPI_STRIDE + c16 * 16);
        __stcs(reinterpret_cast<uint4*>(g_P + (grow0 + row) * SS + nt * 64 + c16 * 8), v);
    }
    if (tid < 128)
        atomicAdd(&g_z[grow0 + tid], zrow[tid]);
}

// ===========================================================================
// column weights: w_k += sum_q P[q,k] / z_q.  Column-partitioned:
// block = (512 q-rows) x (128 cols); 1024 blocks. Streaming (__ldcs) reads.
// ===========================================================================
__global__ __launch_bounds__(256) void col_weights_kernel() {
    __shared__ float izs[512];
    __shared__ float ws[16][128];

    const int tid = threadIdx.x;
    const int r0 = blockIdx.x * 512;
    const int c0 = blockIdx.y * 128;
    const int b  = blockIdx.z;

    for (int i = tid; i < 512; i += 256)
        izs[i] = 1.0f / g_z[(size_t)b * SS + r0 + i];
    __syncthreads();

    const int c8 = tid & 15;
    const int rstripe = tid >> 4;

    float acc[8];
#pragma unroll
    for (int j = 0; j < 8; j++) acc[j] = 0.0f;

    const __nv_bfloat16* Pb = g_P + ((size_t)b * SS + r0 + rstripe) * SS + c0 + c8 * 8;
#pragma unroll 8
    for (int i = 0; i < 32; i++) {
        const float iz = izs[rstripe + i * 16];
        uint4 v = __ldcs(reinterpret_cast<const uint4*>(Pb + (size_t)i * 16 * SS));
        const uint32_t w[4] = {v.x, v.y, v.z, v.w};
#pragma unroll
        for (int h = 0; h < 4; h++) {
            acc[2 * h]     = fmaf(bflo(w[h]), iz, acc[2 * h]);
            acc[2 * h + 1] = fmaf(bfhi(w[h]), iz, acc[2 * h + 1]);
        }
    }

#pragma unroll
    for (int j = 0; j < 8; j++) ws[rstripe][c8 * 8 + j] = acc[j];
    __syncthreads();

    if (tid < 128) {
        float s = 0.0f;
#pragma unroll
        for (int j = 0; j < 16; j++) s += ws[j][tid];
        atomicAdd(&g_w[(size_t)b * SS + c0 + tid], s);
    }
}

// ===========================================================================
// weighted pool: out[b,d] = sum_k w[b,k] * x[b,k,d].
// 512 blocks (32 keys each), 4 independent accumulator chains.
// ===========================================================================
__global__ __launch_bounds__(256) void out_kernel(
    const float* __restrict__ x, float* __restrict__ out)
{
    const int b = blockIdx.y;
    const int k0 = blockIdx.x * 32;
    const int d = threadIdx.x;

    const float* xp = x + ((size_t)b * SS + k0) * DD + d;
    const float* wp = g_w + (size_t)b * SS + k0;

    float a0 = 0.0f, a1 = 0.0f, a2 = 0.0f, a3 = 0.0f;
#pragma unroll
    for (int kk = 0; kk < 32; kk += 4) {
        a0 = fmaf(wp[kk + 0], xp[(size_t)(kk + 0) * DD], a0);
        a1 = fmaf(wp[kk + 1], xp[(size_t)(kk + 1) * DD], a1);
        a2 = fmaf(wp[kk + 2], xp[(size_t)(kk + 2) * DD], a2);
        a3 = fmaf(wp[kk + 3], xp[(size_t)(kk + 3) * DD], a3);
    }
    atomicAdd(&out[b * DD + d], (a0 + a1) + (a2 + a3));
}

// ===========================================================================
extern "C" void kernel_launch(void* const* d_in, const int* in_sizes, int n_in,
                              void* d_out, int out_size) {
    const float* x    = (const float*)d_in[0];
    const float* W    = (const float*)d_in[1];
    const float* bias = (const float*)d_in[2];
    float* out = (float*)d_out;

    cudaFuncSetAttribute(logits_kernel, cudaFuncAttributeMaxDynamicSharedMemorySize, LG_SMEM);
    cudaFuncSetAttribute(proj_kernel, cudaFuncAttributeMaxDynamicSharedMemorySize, PJ_SMEM);

    // 1) fp32 -> bf16 conversion of x, W (+ zeroing)
    convert_kernel<<<(NX4 + D2 * DD / 4 + 255) / 256, 256>>>(x, W, out, out_size);

    // 2) projection (pure-bf16 cp.async pipeline)
    {
        dim3 grid(D2 / 128, (BB * SS) / 128);
        proj_kernel<<<grid, 256, PJ_SMEM>>>(bias);
    }

    // 3) logits + exp + z  (single launch, grid z = BB)
    {
        dim3 grid(SS / 64, SS / 128, BB);
        logits_kernel<<<grid, 256, LG_SMEM>>>();
    }

    // 4) column weights
    {
        dim3 grid(SS / 512, SS / 128, BB);
        col_weights_kernel<<<grid, 256>>>();
    }

    // 5) weighted pool
    out_kernel<<<dim3(SS / 32, BB), 256>>>(x, out);
}